// round 2
// baseline (speedup 1.0000x reference)
#include <cuda_runtime.h>
#include <math.h>

#define S_LEN    4096
#define B_SZ     8
#define HID      768
#define HS_DIM   256   // HIDDEN/3
#define NFREQ    384   // HID/2
#define HS_NFREQ 128   // HS_DIM/2

// Precomputed tables (L2-resident): pe 12 MB, hs_pe 4 MB
__device__ float g_pe[S_LEN * HID];
__device__ float g_hs_pe[S_LEN * HS_DIM];

// ---------------------------------------------------------------------------
// Accurate sincos for |ang| up to ~5000: 3-term Cody-Waite 2*pi reduction
// (FMA chain) followed by MUFU sincos on the reduced argument.
// ---------------------------------------------------------------------------
__device__ __forceinline__ void sincos_red(float ang, float* s, float* c) {
    const double TWO_PI_D = 6.283185307179586476925286766559;
    const float  P1 = 6.28125f;
    const float  P2 = (float)(TWO_PI_D - (double)6.28125f);
    const float  P3 = (float)(TWO_PI_D - (double)6.28125f - (double)((float)(TWO_PI_D - (double)6.28125f)));
    const float  INV2PI = 0.15915494309189535f;
    float k = rintf(ang * INV2PI);
    float r = fmaf(-k, P1, ang);
    r = fmaf(-k, P2, r);
    r = fmaf(-k, P3, r);
    __sincosf(r, s, c);
}

// ---------------------------------------------------------------------------
// Prologue: build BOTH sin tables. One thread per (position, freq) pair.
//   g_pe  : 4096 x 384 float2 pairs (sin,cos interleaved = channels 2k,2k+1)
//   g_hs  : 4096 x 128 float2 pairs
// ---------------------------------------------------------------------------
#define N1 (S_LEN * NFREQ)      // 1,572,864 pe pairs
#define N2 (S_LEN * HS_NFREQ)   //   524,288 hs pairs

__global__ __launch_bounds__(256) void pe_tables_kernel() {
    const int i = blockIdx.x * 256 + threadIdx.x;
    float sv, cv;
    if (i < N1) {
        const float CEXP = (float)(-9.210340371976184 / 768.0); // -ln(1e4)/HID
        int p = i / NFREQ;
        int k = i - p * NFREQ;
        float div = expf((float)(2 * k) * CEXP);
        sincos_red((float)p * div, &sv, &cv);
        ((float2*)g_pe)[i] = make_float2(sv, cv);
    } else {
        const float CEXP = (float)(-9.210340371976184 / 256.0); // -ln(1e4)/HS_DIM
        int j = i - N1;
        int p = j >> 7;
        int k = j & 127;
        float div = expf((float)(2 * k) * CEXP);
        sincos_red((float)p * div, &sv, &cv);
        ((float2*)g_hs_pe)[j] = make_float2(sv, cv);
    }
}

// ---------------------------------------------------------------------------
// Main fused kernel: pure streaming gather + add + LayerNorm.
// No SMEM, no barriers: one warp per (b,s) row, 8 warps per block.
// Per-row L1 wavefronts: word 24 + pe 24 + hs 8 + type 24 + ln 24 + store 24.
// ---------------------------------------------------------------------------
__global__ __launch_bounds__(256) void emb_ln_kernel(
    const int*   __restrict__ input_ids,     // [8,4096]
    const int*   __restrict__ tok_struct,    // [8,4096,3]
    const int*   __restrict__ token_type,    // [8,4096]
    const float* __restrict__ word_emb,      // [30522,768]
    const float* __restrict__ type_emb,      // [2,768]
    const float* __restrict__ ln_w,          // [768]
    const float* __restrict__ ln_b,          // [768]
    float*       __restrict__ out)           // [8,4096,768]
{
    const int tid  = threadIdx.x;
    const int lane = tid & 31;
    const int r    = blockIdx.x * 8 + (tid >> 5);   // row 0..32767
    const int b    = r >> 12;
    const int s    = r & 4095;
    const int idx  = b * S_LEN + s;

    const int tok = __ldg(&input_ids[idx]);
    const int tt  = __ldg(&token_type[idx]);
    const int pp  = __ldg(&tok_struct[idx * 3]);    // para_pos

    const float4* wrow  = (const float4*)(word_emb + (size_t)tok * HID);
    const float4* perow = (const float4*)(g_pe + (size_t)s * HID);
    const float4* hrow  = (const float4*)(g_hs_pe + (size_t)pp * HS_DIM);
    const float4* trow  = (const float4*)(type_emb + tt * HID);

    // hs row: concat(g,g,g) means chunk i uses float4 index (lane+32i)&63,
    // so chunks {0,2,4} and {1,3,5} repeat. Load the two distinct float4s once.
    float4 h[2];
    h[0] = __ldg(&hrow[lane]);
    h[1] = __ldg(&hrow[lane + 32]);

    float4 v[6];
    float sum = 0.f, sumsq = 0.f;
#pragma unroll
    for (int i = 0; i < 6; i++) {
        const int c = lane + 32 * i;
        float4 w4 = __ldg(&wrow[c]);
        float4 p4 = __ldg(&perow[c]);
        float4 t4 = __ldg(&trow[c]);
        float4 h4 = h[i & 1];
        float4 e;
        e.x = (w4.x + h4.x) + (p4.x + t4.x);
        e.y = (w4.y + h4.y) + (p4.y + t4.y);
        e.z = (w4.z + h4.z) + (p4.z + t4.z);
        e.w = (w4.w + h4.w) + (p4.w + t4.w);
        v[i] = e;
        sum   += (e.x + e.y) + (e.z + e.w);
        sumsq += fmaf(e.x, e.x, fmaf(e.y, e.y, fmaf(e.z, e.z, e.w * e.w)));
    }

#pragma unroll
    for (int off = 16; off > 0; off >>= 1) {
        sum   += __shfl_xor_sync(0xFFFFFFFFu, sum,   off);
        sumsq += __shfl_xor_sync(0xFFFFFFFFu, sumsq, off);
    }

    const float inv_n = 1.0f / 768.0f;
    float mu   = sum * inv_n;
    float var  = fmaf(sumsq, inv_n, -mu * mu);
    var = var < 0.f ? 0.f : var;
    float rstd = rsqrtf(var + 1e-12f);

    const float4* wg4 = (const float4*)ln_w;
    const float4* bi4 = (const float4*)ln_b;
    float4* orow = (float4*)(out + (size_t)idx * HID);
#pragma unroll
    for (int i = 0; i < 6; i++) {
        const int c = lane + 32 * i;
        float4 e  = v[i];
        float4 wg = __ldg(&wg4[c]);
        float4 bi = __ldg(&bi4[c]);
        float4 o;
        o.x = fmaf((e.x - mu) * rstd, wg.x, bi.x);
        o.y = fmaf((e.y - mu) * rstd, wg.y, bi.y);
        o.z = fmaf((e.z - mu) * rstd, wg.z, bi.z);
        o.w = fmaf((e.w - mu) * rstd, wg.w, bi.w);
        __stcs(&orow[c], o);   // streaming store: preserve L2 for word_emb
    }
}

// ---------------------------------------------------------------------------
extern "C" void kernel_launch(void* const* d_in, const int* in_sizes, int n_in,
                              void* d_out, int out_size) {
    const int*   input_ids  = (const int*)  d_in[0];
    const int*   tok_struct = (const int*)  d_in[1];
    // d_in[2] = sent_struct_vec (unused by the reference output)
    const int*   token_type = (const int*)  d_in[3];
    const float* word_emb   = (const float*)d_in[4];
    const float* type_emb   = (const float*)d_in[5];
    const float* ln_w       = (const float*)d_in[6];
    const float* ln_b       = (const float*)d_in[7];
    float*       out        = (float*)d_out;

    pe_tables_kernel<<<(N1 + N2) / 256, 256>>>();
    emb_ln_kernel<<<S_LEN * B_SZ / 8, 256>>>(input_ids, tok_struct, token_type,
                                             word_emb, type_emb, ln_w, ln_b, out);
}